// round 2
// baseline (speedup 1.0000x reference)
#include <cuda_runtime.h>
#include <cuda_bf16.h>
#include <math.h>

// ---------------------------------------------------------------------------
// Problem constants
// ---------------------------------------------------------------------------
#define BATCH 4
#define IMG_H 512
#define IMG_W 1408
#define H1 256
#define W1p 704
#define H2 128
#define W2p 352
#define FH 64
#define FW 176
#define NPIX (FH*FW)            // 11264
#define HM_SZ (BATCH*NPIX)      // 45056
#define BEV 512
#define BEV_SZ (BATCH*BEV*BEV)  // 1048576
#define TOPK 200
#define THR 0.15f
#define EPSV 1e-4f

#define OFF_HM     0
#define OFF_DEPTH  (HM_SZ)
#define OFF_LOGITS (2*HM_SZ)
#define OFF_PROB   (2*HM_SZ + BEV_SZ)

// ---------------------------------------------------------------------------
// Scratch buffers (device globals — no allocation allowed)
// ---------------------------------------------------------------------------
__device__ float g_x1[BATCH*32*H1*W1p];     // after conv1
__device__ float g_x2[BATCH*64*H2*W2p];     // after conv2
__device__ float g_feats[BATCH*96*FH*FW];   // after conv3
__device__ float g_h1[BATCH*96*FH*FW];      // heatmap head hidden
__device__ float g_d1[BATCH*96*FH*FW];      // depth head hidden

// ---------------------------------------------------------------------------
// Direct 3x3 conv + BN(eval) + ReLU, register-blocked.
// Each thread: OCPT output channels x PX pixels (pixels interleaved by NTX so
// global loads are coalesced). Weights staged in SMEM, loaded into a register
// once per (ic,ky,kx,oc) and reused across PX pixels.
// DUAL=1: blockIdx.z selects between two heads (two weight sets / outputs).
// ---------------------------------------------------------------------------
template<int IC, int OC, int OCPT, int STRIDE, int PX, int NTX, int NTY, int DUAL>
__global__ void __launch_bounds__(NTX*NTY, 2)
conv3x3_v2(const float* __restrict__ in,
           const float* __restrict__ w0, const float* __restrict__ ga0,
           const float* __restrict__ be0, float* __restrict__ out0,
           const float* __restrict__ w1, const float* __restrict__ ga1,
           const float* __restrict__ be1, float* __restrict__ out1,
           int IH, int IW, int OH, int OW)
{
    constexpr int NG  = OC / OCPT;
    constexpr int NIN = 3;                    // taps per pixel per row

    int z = blockIdx.z;
    const int g = z % NG;  z /= NG;
    int head = 0;
    if (DUAL) { head = z & 1; z >>= 1; }
    const int b = z;

    const float* wgt   = (DUAL && head) ? w1  : w0;
    const float* gamma = (DUAL && head) ? ga1 : ga0;
    const float* beta  = (DUAL && head) ? be1 : be0;
    float*       out   = (DUAL && head) ? out1 : out0;

    const int oy = blockIdx.y * NTY + threadIdx.y;
    const int x0 = blockIdx.x * (NTX * PX) + threadIdx.x;  // pixel p at x0 + p*NTX

    __shared__ float ws[OCPT * IC * 9];
    {
        const int tid = threadIdx.y * NTX + threadIdx.x;
        const float* wsrc = wgt + (size_t)(g * OCPT) * IC * 9;
        for (int i = tid; i < OCPT * IC * 9; i += NTX * NTY)
            ws[i] = wsrc[i];
    }
    __syncthreads();

    float acc[OCPT][PX];
#pragma unroll
    for (int o = 0; o < OCPT; o++)
#pragma unroll
        for (int p = 0; p < PX; p++) acc[o][p] = 0.f;

    const float* inb = in + (size_t)b * IC * IH * IW;

#pragma unroll 1
    for (int ic = 0; ic < IC; ic++) {
        const float* inc = inb + (size_t)ic * IH * IW;
        const float* wsc = ws + ic * 9;
#pragma unroll
        for (int ky = 0; ky < 3; ky++) {
            const int iy = oy * STRIDE - 1 + ky;
            const bool yok = (iy >= 0) & (iy < IH);
            const float* row = inc + (size_t)iy * IW;

            float iv[PX][NIN];
#pragma unroll
            for (int p = 0; p < PX; p++) {
#pragma unroll
                for (int j = 0; j < NIN; j++) {
                    const int ix = (x0 + p * NTX) * STRIDE - 1 + j;
                    iv[p][j] = (yok && ix >= 0 && ix < IW) ? row[ix] : 0.f;
                }
            }
#pragma unroll
            for (int kx = 0; kx < 3; kx++) {
#pragma unroll
                for (int o = 0; o < OCPT; o++) {
                    const float w = wsc[o * IC * 9 + ky * 3 + kx];
#pragma unroll
                    for (int p = 0; p < PX; p++)
                        acc[o][p] = fmaf(iv[p][kx], w, acc[o][p]);
                }
            }
        }
    }

    const float inv = rsqrtf(1.f + 1e-5f);
#pragma unroll
    for (int o = 0; o < OCPT; o++) {
        const int oc = g * OCPT + o;
        const float sc = gamma[oc] * inv;
        const float bi = beta[oc];
        float* orow = out + (((size_t)b * OC + oc) * OH + oy) * OW;
#pragma unroll
        for (int p = 0; p < PX; p++) {
            const float v = fmaf(acc[o][p], sc, bi);
            orow[x0 + p * NTX] = fmaxf(v, 0.f);
        }
    }
}

// ---------------------------------------------------------------------------
// 1x1 conv (96 -> 1) + bias.  mode 0: raw logits (hm). mode 1: depth transform.
// ---------------------------------------------------------------------------
template<int MODE>
__global__ void head1x1(const float* __restrict__ feat,
                        const float* __restrict__ w,
                        const float* __restrict__ bias,
                        float* __restrict__ out)
{
    const int idx = blockIdx.x * blockDim.x + threadIdx.x;
    if (idx >= BATCH * NPIX) return;
    const int b = idx / NPIX;
    const int p = idx % NPIX;
    float s = bias[0];
    const float* fb = feat + (size_t)b * 96 * NPIX + p;
#pragma unroll 8
    for (int ic = 0; ic < 96; ic++)
        s += fb[(size_t)ic * NPIX] * w[ic];
    if (MODE == 0) {
        out[idx] = s;
    } else {
        const float sig = 1.f / (1.f + expf(-s));
        out[idx] = 1.0f + sig * 79.0f;   // DMIN + sig*(DMAX-DMIN)
    }
}

// ---------------------------------------------------------------------------
// Zero the BEV accumulation region
// ---------------------------------------------------------------------------
__global__ void zero_bev(float* __restrict__ bev)
{
    const int i = blockIdx.x * blockDim.x + threadIdx.x;
    if (i < BEV_SZ) bev[i] = 0.f;
}

// ---------------------------------------------------------------------------
// Per-batch top-200 (iterative block argmax, lowest-index tie break) + splat.
// ---------------------------------------------------------------------------
__global__ void __launch_bounds__(1024, 1)
topk_splat(const float* __restrict__ hm,
           const float* __restrict__ depth,
           const float* __restrict__ P,
           const float* __restrict__ T,
           float* __restrict__ bev)
{
    const int b    = blockIdx.x;
    const int tid  = threadIdx.x;
    const int lane = tid & 31;
    const int warp = tid >> 5;

    __shared__ float prob[NPIX];
    __shared__ float sscore[TOPK];
    __shared__ int   sidx[TOPK];
    __shared__ float wv[32];
    __shared__ int   wi[32];

    for (int i = tid; i < NPIX; i += blockDim.x) {
        const float x = hm[b * NPIX + i];
        prob[i] = 1.f / (1.f + expf(-x));
    }
    __syncthreads();

    for (int k = 0; k < TOPK; k++) {
        float v = -1.f; int bi = NPIX;
        for (int i = tid; i < NPIX; i += blockDim.x) {
            const float p = prob[i];
            if (p > v || (p == v && i < bi)) { v = p; bi = i; }
        }
#pragma unroll
        for (int off = 16; off > 0; off >>= 1) {
            const float ov = __shfl_down_sync(0xffffffffu, v, off);
            const int   oi = __shfl_down_sync(0xffffffffu, bi, off);
            if (ov > v || (ov == v && oi < bi)) { v = ov; bi = oi; }
        }
        if (lane == 0) { wv[warp] = v; wi[warp] = bi; }
        __syncthreads();
        if (warp == 0) {
            v  = wv[lane];
            bi = wi[lane];
#pragma unroll
            for (int off = 16; off > 0; off >>= 1) {
                const float ov = __shfl_down_sync(0xffffffffu, v, off);
                const int   oi = __shfl_down_sync(0xffffffffu, bi, off);
                if (ov > v || (ov == v && oi < bi)) { v = ov; bi = oi; }
            }
            if (lane == 0) {
                sscore[k] = v;
                sidx[k]   = bi;
                prob[bi]  = -1.f;
            }
        }
        __syncthreads();
    }

    if (tid < TOPK) {
        const int   idx   = sidx[tid];
        const float score = sscore[tid];
        const int ys = idx / FW;
        const int xs = idx % FW;
        const float d = depth[b * NPIX + idx];
        const float u = (xs + 0.5f) * ((float)IMG_W / (float)FW);
        const float v = (ys + 0.5f) * ((float)IMG_H / (float)FH);

        const float* Pb = P + b * 12;
        const float fx = fmaxf(Pb[0], EPSV);
        const float fy = fmaxf(Pb[5], EPSV);
        const float cx = Pb[2], cy = Pb[6];
        const float tx = Pb[3], ty = Pb[7];
        const float xc = (u * d - cx * d - tx) / fx;
        const float yc = (v * d - cy * d - ty) / fy;

        const float* Tb = T + b * 16;
        const float lx = Tb[0]*xc + Tb[1]*yc + Tb[2]*d + Tb[3];
        const float ly = Tb[4]*xc + Tb[5]*yc + Tb[6]*d + Tb[7];

        const int gx = (int)floorf((lx + 51.2f) / 0.2f);
        const int gy = (int)floorf((ly + 51.2f) / 0.2f);

        const bool valid = (score >= THR) && (gx >= 0) && (gx < BEV)
                                          && (gy >= 0) && (gy < BEV);
        if (valid) {
            const float isig = 18.f / 25.f;   // 1/(2*sigma^2), sigma=5/6
            float* bb = bev + (size_t)b * BEV * BEV;
#pragma unroll
            for (int dy = -2; dy <= 2; dy++) {
                const int iy = gy + dy;
                if (iy < 0 || iy >= BEV) continue;
#pragma unroll
                for (int dx = -2; dx <= 2; dx++) {
                    const int ix = gx + dx;
                    if (ix < 0 || ix >= BEV) continue;
                    const float val = score * expf(-(float)(dy*dy + dx*dx) * isig);
                    atomicMax((int*)&bb[iy * BEV + ix], __float_as_int(val));
                }
            }
        }
    }
}

// ---------------------------------------------------------------------------
// Finalize: clip to prob, compute logits.
// ---------------------------------------------------------------------------
__global__ void finalize_bev(float* __restrict__ out)
{
    const int i = blockIdx.x * blockDim.x + threadIdx.x;
    if (i >= BEV_SZ) return;
    float p = out[OFF_PROB + i];
    p = fminf(fmaxf(p, EPSV), 1.f - EPSV);
    out[OFF_PROB + i]   = p;
    out[OFF_LOGITS + i] = logf(p) - log1pf(-p);
}

// ---------------------------------------------------------------------------
// Launcher
// ---------------------------------------------------------------------------
extern "C" void kernel_launch(void* const* d_in, const int* in_sizes, int n_in,
                              void* d_out, int out_size)
{
    (void)in_sizes; (void)n_in; (void)out_size;

    const float* image = (const float*)d_in[0];
    const float* P     = (const float*)d_in[1];
    const float* T     = (const float*)d_in[2];
    const float* W1  = (const float*)d_in[3];
    const float* g1  = (const float*)d_in[4];
    const float* b1  = (const float*)d_in[5];
    const float* W2  = (const float*)d_in[6];
    const float* g2  = (const float*)d_in[7];
    const float* b2  = (const float*)d_in[8];
    const float* W3  = (const float*)d_in[9];
    const float* g3  = (const float*)d_in[10];
    const float* b3  = (const float*)d_in[11];
    const float* Wh1 = (const float*)d_in[12];
    const float* gh1 = (const float*)d_in[13];
    const float* bh1 = (const float*)d_in[14];
    const float* Wh2 = (const float*)d_in[15];
    const float* bh2 = (const float*)d_in[16];
    const float* Wd1 = (const float*)d_in[17];
    const float* gd1 = (const float*)d_in[18];
    const float* bd1 = (const float*)d_in[19];
    const float* Wd2 = (const float*)d_in[20];
    const float* bd2 = (const float*)d_in[21];

    float* out = (float*)d_out;

    float *x1, *x2, *feats, *h1, *d1;
    cudaGetSymbolAddress((void**)&x1,    g_x1);
    cudaGetSymbolAddress((void**)&x2,    g_x2);
    cudaGetSymbolAddress((void**)&feats, g_feats);
    cudaGetSymbolAddress((void**)&h1,    g_h1);
    cudaGetSymbolAddress((void**)&d1,    g_d1);

    // conv1: 3 -> 32, stride 2   (512x1408 -> 256x704)
    {
        dim3 blk(88, 2);
        dim3 grd(1, H1 / 2, BATCH * (32 / 8));
        conv3x3_v2<3, 32, 8, 2, 8, 88, 2, 0><<<grd, blk>>>(
            image, W1, g1, b1, x1, nullptr, nullptr, nullptr, nullptr,
            IMG_H, IMG_W, H1, W1p);
    }
    // conv2: 32 -> 64, stride 2  (256x704 -> 128x352)
    {
        dim3 blk(44, 4);
        dim3 grd(1, H2 / 4, BATCH * (64 / 8));
        conv3x3_v2<32, 64, 8, 2, 8, 44, 4, 0><<<grd, blk>>>(
            x1, W2, g2, b2, x2, nullptr, nullptr, nullptr, nullptr,
            H1, W1p, H2, W2p);
    }
    // conv3: 64 -> 96, stride 2  (128x352 -> 64x176)
    {
        dim3 blk(22, 8);
        dim3 grd(1, FH / 8, BATCH * (96 / 8));
        conv3x3_v2<64, 96, 8, 2, 8, 22, 8, 0><<<grd, blk>>>(
            x2, W3, g3, b3, feats, nullptr, nullptr, nullptr, nullptr,
            H2, W2p, FH, FW);
    }
    // both head hidden convs in one launch: 96 -> 96, stride 1, pad 1
    {
        dim3 blk(22, 8);
        dim3 grd(1, FH / 8, BATCH * 2 * (96 / 8));
        conv3x3_v2<96, 96, 8, 1, 8, 22, 8, 1><<<grd, blk>>>(
            feats, Wh1, gh1, bh1, h1, Wd1, gd1, bd1, d1,
            FH, FW, FH, FW);
    }
    // hm 1x1 -> d_out[OFF_HM]
    head1x1<0><<<(BATCH * NPIX + 255) / 256, 256>>>(h1, Wh2, bh2, out + OFF_HM);
    // depth 1x1 + transform -> d_out[OFF_DEPTH]
    head1x1<1><<<(BATCH * NPIX + 255) / 256, 256>>>(d1, Wd2, bd2, out + OFF_DEPTH);

    // BEV accumulate (prob region), splat, finalize
    zero_bev<<<(BEV_SZ + 255) / 256, 256>>>(out + OFF_PROB);
    topk_splat<<<BATCH, 1024>>>(out + OFF_HM, out + OFF_DEPTH, P, T, out + OFF_PROB);
    finalize_bev<<<(BEV_SZ + 255) / 256, 256>>>(out);
}

// round 3
// speedup vs baseline: 2.5443x; 2.5443x over previous
#include <cuda_runtime.h>
#include <cuda_bf16.h>
#include <math.h>
#include <string.h>

// ---------------------------------------------------------------------------
// Problem constants
// ---------------------------------------------------------------------------
#define BATCH 4
#define IMG_H 512
#define IMG_W 1408
#define FH 64
#define FW 176
#define NPIX (FH*FW)            // 11264
#define HM_SZ (BATCH*NPIX)      // 45056
#define BEV 512
#define BEV_SZ (BATCH*BEV*BEV)  // 1048576
#define TOPK 200
#define THR 0.15f
#define EPSV 1e-4f

#define OFF_HM     0
#define OFF_DEPTH  (HM_SZ)
#define OFF_LOGITS (2*HM_SZ)
#define OFF_PROB   (2*HM_SZ + BEV_SZ)

// Padded geometry (1-px halo, width padded to mult of 4)
#define PW0 1412
#define PH0 514
#define PLANE0 (PH0*PW0)        // image: 3 ch
#define PW1 708
#define PH1 258
#define PLANE1 (PH1*PW1)        // x1: 32 ch, 256x704
#define PW2 356
#define PH2 130
#define PLANE2 (PH2*PW2)        // x2: 64 ch, 128x352
#define PW3 180
#define PH3 66
#define PLANE3 (PH3*PW3)        // feats/h1/d1: 96 ch, 64x176

// ---------------------------------------------------------------------------
// Scratch (device globals: zero-initialized at module load; halos never
// written by any kernel, so they remain zero across all graph replays)
// ---------------------------------------------------------------------------
__device__ float g_imgp[BATCH*3*PLANE0 + 2048];
__device__ float g_x1[BATCH*32*PLANE1 + 2048];
__device__ float g_x2[BATCH*64*PLANE2 + 2048];
__device__ float g_feats[BATCH*96*PLANE3 + 2048];
__device__ float g_h1[BATCH*96*PLANE3 + 2048];
__device__ float g_d1[BATCH*96*PLANE3 + 2048];

// ---------------------------------------------------------------------------
// f32x2 packed math helpers
// ---------------------------------------------------------------------------
__device__ __forceinline__ unsigned long long pack2(float x) {
    unsigned long long r;
    const unsigned int u = __float_as_uint(x);
    asm("mov.b64 %0, {%1, %1};" : "=l"(r) : "r"(u));
    return r;
}
#define FMA2(acc, a, b) \
    asm("fma.rn.f32x2 %0, %1, %2, %0;" : "+l"(acc) : "l"(a), "l"(b))

// ---------------------------------------------------------------------------
// Padded direct 3x3 conv + BN(eval) + ReLU using packed f32x2 FMAs.
// Pack axis = output-channel pairs. Block (32,4): warp w -> output row,
// lane l -> PX consecutive output pixels. Inputs/outputs in padded layout.
// DUAL=1: blockIdx.z low bit selects head (two weight sets / outputs).
// ---------------------------------------------------------------------------
#define PXC 6
template<int IC, int OC, int OCPT, int STRIDE, int DUAL>
__global__ void __launch_bounds__(128, 4)
convp(const float* __restrict__ in, int PWI, int planeI,
      int OH, int OW, int PWO, int planeO,
      const float* __restrict__ w0, const float* __restrict__ ga0,
      const float* __restrict__ be0, float* __restrict__ out0,
      const float* __restrict__ w1, const float* __restrict__ ga1,
      const float* __restrict__ be1, float* __restrict__ out1)
{
    constexpr int NG  = OC / OCPT;
    constexpr int NOP = OCPT / 2;                 // oc pairs per thread
    constexpr int NIN = (PXC - 1) * STRIDE + 3;   // input cols used per row
    constexpr int NV2 = (NIN + 1) / 2;            // float2 loads per row

    int z = blockIdx.z;
    const int g = z % NG;  z /= NG;
    int head = 0;
    if (DUAL) { head = z & 1; z >>= 1; }
    const int b = z;

    const float* wgt   = (DUAL && head) ? w1  : w0;
    const float* gamma = (DUAL && head) ? ga1 : ga0;
    const float* beta  = (DUAL && head) ? be1 : be0;
    float*       out   = (DUAL && head) ? out1 : out0;

    const int l  = threadIdx.x;
    const int oy = blockIdx.y * 4 + threadIdx.y;
    const int x0 = (blockIdx.x * 32 + l) * PXC;

    // weights staged channel-interleaved: ws[(ic*9 + tap)*OCPT + ocl]
    __shared__ float ws[IC * 9 * OCPT];
    {
        const int tid = threadIdx.y * 32 + l;
        for (int i = tid; i < IC * 9 * OCPT; i += 128) {
            const int ocl = i % OCPT;
            const int t   = (i / OCPT) % 9;
            const int ic  = i / (OCPT * 9);
            ws[i] = wgt[((size_t)(g * OCPT + ocl) * IC + ic) * 9 + t];
        }
    }
    __syncthreads();

    unsigned long long acc[NOP][PXC];
#pragma unroll
    for (int op = 0; op < NOP; op++)
#pragma unroll
        for (int p = 0; p < PXC; p++) acc[op][p] = 0ULL;

    const float* inb = in + (size_t)b * IC * planeI;

#pragma unroll 1
    for (int ic = 0; ic < IC; ic++) {
        const float* plane = inb + (size_t)ic * planeI;
#pragma unroll
        for (int ky = 0; ky < 3; ky++) {
            const float* rp = plane + (size_t)(oy * STRIDE + ky) * PWI
                                    + (size_t)x0 * STRIDE;
            unsigned long long pk[NIN];
            {
                float v[NV2 * 2];
#pragma unroll
                for (int i = 0; i < NV2; i++) {
                    const float2 t2 = *(const float2*)(rp + 2 * i);
                    v[2 * i]     = t2.x;
                    v[2 * i + 1] = t2.y;
                }
#pragma unroll
                for (int c = 0; c < NIN; c++) pk[c] = pack2(v[c]);
            }
#pragma unroll
            for (int kx = 0; kx < 3; kx++) {
                const float* wr = ws + (ic * 9 + ky * 3 + kx) * OCPT;
                unsigned long long w2[NOP];
#pragma unroll
                for (int op = 0; op < NOP; op++) {
                    const float2 wf = *(const float2*)(wr + 2 * op);
                    unsigned long long t;
                    memcpy(&t, &wf, 8);
                    w2[op] = t;
                }
#pragma unroll
                for (int p = 0; p < PXC; p++) {
                    const unsigned long long xv = pk[p * STRIDE + kx];
#pragma unroll
                    for (int op = 0; op < NOP; op++)
                        FMA2(acc[op][p], w2[op], xv);
                }
            }
        }
    }

    const float inv = rsqrtf(1.f + 1e-5f);
#pragma unroll
    for (int op = 0; op < NOP; op++) {
        const int oc = g * OCPT + 2 * op;
        const float s0 = gamma[oc] * inv,  s1 = gamma[oc + 1] * inv;
        const float c0 = beta[oc],         c1 = beta[oc + 1];
        float* o0 = out + (size_t)(b * OC + oc) * planeO
                        + (size_t)(oy + 1) * PWO + 1;
        float* o1 = o0 + planeO;
#pragma unroll
        for (int p = 0; p < PXC; p++) {
            if (x0 + p < OW) {
                float2 a;
                memcpy(&a, &acc[op][p], 8);
                o0[x0 + p] = fmaxf(fmaf(a.x, s0, c0), 0.f);
                o1[x0 + p] = fmaxf(fmaf(a.y, s1, c1), 0.f);
            }
        }
    }
}

// ---------------------------------------------------------------------------
// Copy image into padded scratch (interior only; halo stays zero)
// ---------------------------------------------------------------------------
__global__ void pad_image(const float* __restrict__ img)
{
    const int idx = blockIdx.x * blockDim.x + threadIdx.x;
    const int total = BATCH * 3 * IMG_H * IMG_W;
    if (idx >= total) return;
    const int x = idx % IMG_W;
    int r = idx / IMG_W;
    const int y = r % IMG_H;
    const int p = r / IMG_H;          // b*3 + c
    g_imgp[(size_t)p * PLANE0 + (size_t)(y + 1) * PW0 + (x + 1)] = img[idx];
}

// ---------------------------------------------------------------------------
// 1x1 conv (96 -> 1) + bias (reads padded feature maps).
// mode 0: raw logits (hm). mode 1: depth transform.
// ---------------------------------------------------------------------------
template<int MODE>
__global__ void head1x1(const float* __restrict__ feat,
                        const float* __restrict__ w,
                        const float* __restrict__ bias,
                        float* __restrict__ out)
{
    const int idx = blockIdx.x * blockDim.x + threadIdx.x;
    if (idx >= BATCH * NPIX) return;
    const int b = idx / NPIX;
    const int p = idx % NPIX;
    const int y = p / FW;
    const int x = p % FW;
    float s = bias[0];
    const float* fb = feat + (size_t)b * 96 * PLANE3
                           + (size_t)(y + 1) * PW3 + (x + 1);
#pragma unroll 8
    for (int ic = 0; ic < 96; ic++)
        s += fb[(size_t)ic * PLANE3] * w[ic];
    if (MODE == 0) {
        out[idx] = s;
    } else {
        const float sig = 1.f / (1.f + expf(-s));
        out[idx] = 1.0f + sig * 79.0f;   // DMIN + sig*(DMAX-DMIN)
    }
}

// ---------------------------------------------------------------------------
// Zero the BEV accumulation region
// ---------------------------------------------------------------------------
__global__ void zero_bev(float* __restrict__ bev)
{
    const int i = blockIdx.x * blockDim.x + threadIdx.x;
    if (i < BEV_SZ) bev[i] = 0.f;
}

// ---------------------------------------------------------------------------
// Per-batch top-200 (iterative block argmax, lowest-index tie break) + splat.
// ---------------------------------------------------------------------------
__global__ void __launch_bounds__(1024, 1)
topk_splat(const float* __restrict__ hm,
           const float* __restrict__ depth,
           const float* __restrict__ P,
           const float* __restrict__ T,
           float* __restrict__ bev)
{
    const int b    = blockIdx.x;
    const int tid  = threadIdx.x;
    const int lane = tid & 31;
    const int warp = tid >> 5;

    __shared__ float prob[NPIX];
    __shared__ float sscore[TOPK];
    __shared__ int   sidx[TOPK];
    __shared__ float wv[32];
    __shared__ int   wi[32];

    for (int i = tid; i < NPIX; i += blockDim.x) {
        const float x = hm[b * NPIX + i];
        prob[i] = 1.f / (1.f + expf(-x));
    }
    __syncthreads();

    for (int k = 0; k < TOPK; k++) {
        float v = -1.f; int bi = NPIX;
        for (int i = tid; i < NPIX; i += blockDim.x) {
            const float p = prob[i];
            if (p > v || (p == v && i < bi)) { v = p; bi = i; }
        }
#pragma unroll
        for (int off = 16; off > 0; off >>= 1) {
            const float ov = __shfl_down_sync(0xffffffffu, v, off);
            const int   oi = __shfl_down_sync(0xffffffffu, bi, off);
            if (ov > v || (ov == v && oi < bi)) { v = ov; bi = oi; }
        }
        if (lane == 0) { wv[warp] = v; wi[warp] = bi; }
        __syncthreads();
        if (warp == 0) {
            v  = wv[lane];
            bi = wi[lane];
#pragma unroll
            for (int off = 16; off > 0; off >>= 1) {
                const float ov = __shfl_down_sync(0xffffffffu, v, off);
                const int   oi = __shfl_down_sync(0xffffffffu, bi, off);
                if (ov > v || (ov == v && oi < bi)) { v = ov; bi = oi; }
            }
            if (lane == 0) {
                sscore[k] = v;
                sidx[k]   = bi;
                prob[bi]  = -1.f;
            }
        }
        __syncthreads();
    }

    if (tid < TOPK) {
        const int   idx   = sidx[tid];
        const float score = sscore[tid];
        const int ys = idx / FW;
        const int xs = idx % FW;
        const float d = depth[b * NPIX + idx];
        const float u = (xs + 0.5f) * ((float)IMG_W / (float)FW);
        const float v = (ys + 0.5f) * ((float)IMG_H / (float)FH);

        const float* Pb = P + b * 12;
        const float fx = fmaxf(Pb[0], EPSV);
        const float fy = fmaxf(Pb[5], EPSV);
        const float cx = Pb[2], cy = Pb[6];
        const float tx = Pb[3], ty = Pb[7];
        const float xc = (u * d - cx * d - tx) / fx;
        const float yc = (v * d - cy * d - ty) / fy;

        const float* Tb = T + b * 16;
        const float lx = Tb[0]*xc + Tb[1]*yc + Tb[2]*d + Tb[3];
        const float ly = Tb[4]*xc + Tb[5]*yc + Tb[6]*d + Tb[7];

        const int gx = (int)floorf((lx + 51.2f) / 0.2f);
        const int gy = (int)floorf((ly + 51.2f) / 0.2f);

        const bool valid = (score >= THR) && (gx >= 0) && (gx < BEV)
                                          && (gy >= 0) && (gy < BEV);
        if (valid) {
            const float isig = 18.f / 25.f;   // 1/(2*sigma^2), sigma=5/6
            float* bb = bev + (size_t)b * BEV * BEV;
#pragma unroll
            for (int dy = -2; dy <= 2; dy++) {
                const int iy = gy + dy;
                if (iy < 0 || iy >= BEV) continue;
#pragma unroll
                for (int dx = -2; dx <= 2; dx++) {
                    const int ix = gx + dx;
                    if (ix < 0 || ix >= BEV) continue;
                    const float val = score * expf(-(float)(dy*dy + dx*dx) * isig);
                    atomicMax((int*)&bb[iy * BEV + ix], __float_as_int(val));
                }
            }
        }
    }
}

// ---------------------------------------------------------------------------
// Finalize: clip to prob, compute logits.
// ---------------------------------------------------------------------------
__global__ void finalize_bev(float* __restrict__ out)
{
    const int i = blockIdx.x * blockDim.x + threadIdx.x;
    if (i >= BEV_SZ) return;
    float p = out[OFF_PROB + i];
    p = fminf(fmaxf(p, EPSV), 1.f - EPSV);
    out[OFF_PROB + i]   = p;
    out[OFF_LOGITS + i] = logf(p) - log1pf(-p);
}

// ---------------------------------------------------------------------------
// Launcher
// ---------------------------------------------------------------------------
extern "C" void kernel_launch(void* const* d_in, const int* in_sizes, int n_in,
                              void* d_out, int out_size)
{
    (void)in_sizes; (void)n_in; (void)out_size;

    const float* image = (const float*)d_in[0];
    const float* P     = (const float*)d_in[1];
    const float* T     = (const float*)d_in[2];
    const float* W1  = (const float*)d_in[3];
    const float* g1  = (const float*)d_in[4];
    const float* b1  = (const float*)d_in[5];
    const float* W2  = (const float*)d_in[6];
    const float* g2  = (const float*)d_in[7];
    const float* b2  = (const float*)d_in[8];
    const float* W3  = (const float*)d_in[9];
    const float* g3  = (const float*)d_in[10];
    const float* b3  = (const float*)d_in[11];
    const float* Wh1 = (const float*)d_in[12];
    const float* gh1 = (const float*)d_in[13];
    const float* bh1 = (const float*)d_in[14];
    const float* Wh2 = (const float*)d_in[15];
    const float* bh2 = (const float*)d_in[16];
    const float* Wd1 = (const float*)d_in[17];
    const float* gd1 = (const float*)d_in[18];
    const float* bd1 = (const float*)d_in[19];
    const float* Wd2 = (const float*)d_in[20];
    const float* bd2 = (const float*)d_in[21];

    float* out = (float*)d_out;

    float *imgp, *x1, *x2, *feats, *h1, *d1;
    cudaGetSymbolAddress((void**)&imgp,  g_imgp);
    cudaGetSymbolAddress((void**)&x1,    g_x1);
    cudaGetSymbolAddress((void**)&x2,    g_x2);
    cudaGetSymbolAddress((void**)&feats, g_feats);
    cudaGetSymbolAddress((void**)&h1,    g_h1);
    cudaGetSymbolAddress((void**)&d1,    g_d1);

    // pad image into halo scratch
    {
        const int total = BATCH * 3 * IMG_H * IMG_W;
        pad_image<<<(total + 255) / 256, 256>>>(image);
    }

    dim3 blk(32, 4);

    // conv1: 3 -> 32, stride 2  (512x1408 -> 256x704)
    convp<3, 32, 8, 2, 0><<<dim3(4, 64, BATCH * 4), blk>>>(
        imgp, PW0, PLANE0, 256, 704, PW1, PLANE1,
        W1, g1, b1, x1, nullptr, nullptr, nullptr, nullptr);

    // conv2: 32 -> 64, stride 2  (256x704 -> 128x352)
    convp<32, 64, 8, 2, 0><<<dim3(2, 32, BATCH * 8), blk>>>(
        x1, PW1, PLANE1, 128, 352, PW2, PLANE2,
        W2, g2, b2, x2, nullptr, nullptr, nullptr, nullptr);

    // conv3: 64 -> 96, stride 2  (128x352 -> 64x176)
    convp<64, 96, 8, 2, 0><<<dim3(1, 16, BATCH * 12), blk>>>(
        x2, PW2, PLANE2, 64, 176, PW3, PLANE3,
        W3, g3, b3, feats, nullptr, nullptr, nullptr, nullptr);

    // both head hidden convs (fused): 96 -> 96, stride 1
    convp<96, 96, 8, 1, 1><<<dim3(1, 16, BATCH * 2 * 12), blk>>>(
        feats, PW3, PLANE3, 64, 176, PW3, PLANE3,
        Wh1, gh1, bh1, h1, Wd1, gd1, bd1, d1);

    // 1x1 heads
    head1x1<0><<<(BATCH * NPIX + 255) / 256, 256>>>(h1, Wh2, bh2, out + OFF_HM);
    head1x1<1><<<(BATCH * NPIX + 255) / 256, 256>>>(d1, Wd2, bd2, out + OFF_DEPTH);

    // BEV accumulate (prob region), splat, finalize
    zero_bev<<<(BEV_SZ + 255) / 256, 256>>>(out + OFF_PROB);
    topk_splat<<<BATCH, 1024>>>(out + OFF_HM, out + OFF_DEPTH, P, T, out + OFF_PROB);
    finalize_bev<<<(BEV_SZ + 255) / 256, 256>>>(out);
}

// round 4
// speedup vs baseline: 2.7923x; 1.0975x over previous
#include <cuda_runtime.h>
#include <cuda_bf16.h>
#include <math.h>
#include <string.h>

// ---------------------------------------------------------------------------
// Problem constants
// ---------------------------------------------------------------------------
#define BATCH 4
#define IMG_H 512
#define IMG_W 1408
#define FH 64
#define FW 176
#define NPIX (FH*FW)            // 11264
#define HM_SZ (BATCH*NPIX)      // 45056
#define BEV 512
#define BEV_SZ (BATCH*BEV*BEV)  // 1048576
#define TOPK 200
#define THR 0.15f
#define EPSV 1e-4f

#define OFF_HM     0
#define OFF_DEPTH  (HM_SZ)
#define OFF_LOGITS (2*HM_SZ)
#define OFF_PROB   (2*HM_SZ + BEV_SZ)

// Padded geometry (1-px halo, width padded to mult of 4)
#define PW0 1412
#define PH0 514
#define PLANE0 (PH0*PW0)        // image: 3 ch
#define PW1 708
#define PH1 258
#define PLANE1 (PH1*PW1)        // x1: 32 ch, 256x704
#define PW2 356
#define PH2 130
#define PLANE2 (PH2*PW2)        // x2: 64 ch, 128x352
#define PW3 180
#define PH3 66
#define PLANE3 (PH3*PW3)        // feats/h1/d1: 96 ch, 64x176

// ---------------------------------------------------------------------------
// Scratch (device globals: zero-initialized at module load; halos never
// written by any kernel, so they remain zero across all graph replays)
// ---------------------------------------------------------------------------
__device__ float g_imgp[BATCH*3*PLANE0 + 4096];
__device__ float g_x1[BATCH*32*PLANE1 + 4096];
__device__ float g_x2[BATCH*64*PLANE2 + 4096];
__device__ float g_feats[BATCH*96*PLANE3 + 4096];
__device__ float g_h1[BATCH*96*PLANE3 + 4096];
__device__ float g_d1[BATCH*96*PLANE3 + 4096];

// ---------------------------------------------------------------------------
// f32x2 packed math helpers
// ---------------------------------------------------------------------------
__device__ __forceinline__ unsigned long long pack2(float x) {
    unsigned long long r;
    const unsigned int u = __float_as_uint(x);
    asm("mov.b64 %0, {%1, %1};" : "=l"(r) : "r"(u));
    return r;
}
#define FMA2(acc, a, b) \
    asm("fma.rn.f32x2 %0, %1, %2, %0;" : "+l"(acc) : "l"(a), "l"(b))

// ---------------------------------------------------------------------------
// Padded direct 3x3 conv + BN(eval) + ReLU using packed f32x2 FMAs.
// Pack axis = output-channel pairs (OCPT channels = NOP pairs per thread).
// Block (32,4): warp -> output row, lane -> PXC consecutive output pixels.
// Weights staged channel-interleaved in SMEM, fetched as float4 (2 pairs).
// DUAL=1: blockIdx.z selects head (two weight sets / outputs).
// ---------------------------------------------------------------------------
template<int IC, int OC, int OCPT, int STRIDE, int PXC, int DUAL>
__global__ void __launch_bounds__(128, 4)
convp(const float* __restrict__ in, int PWI, int planeI,
      int OH, int OW, int PWO, int planeO,
      const float* __restrict__ w0, const float* __restrict__ ga0,
      const float* __restrict__ be0, float* __restrict__ out0,
      const float* __restrict__ w1, const float* __restrict__ ga1,
      const float* __restrict__ be1, float* __restrict__ out1)
{
    constexpr int NG  = OC / OCPT;
    constexpr int NOP = OCPT / 2;                 // oc pairs per thread
    constexpr int NF4 = NOP / 2;                  // float4 weight loads per tap
    constexpr int NIN = (PXC - 1) * STRIDE + 3;   // input cols used per row
    constexpr int NV2 = (NIN + 1) / 2;            // float2 loads per row

    int z = blockIdx.z;
    const int g = z % NG;  z /= NG;
    int head = 0;
    if (DUAL) { head = z & 1; z >>= 1; }
    const int b = z;

    const float* wgt   = (DUAL && head) ? w1  : w0;
    const float* gamma = (DUAL && head) ? ga1 : ga0;
    const float* beta  = (DUAL && head) ? be1 : be0;
    float*       out   = (DUAL && head) ? out1 : out0;

    const int l  = threadIdx.x;
    const int oy = blockIdx.y * 4 + threadIdx.y;
    const int x0 = (blockIdx.x * 32 + l) * PXC;

    // weights staged channel-interleaved: ws[(ic*9 + tap)*OCPT + ocl]
    __shared__ __align__(16) float ws[IC * 9 * OCPT];
    {
        const int tid = threadIdx.y * 32 + l;
        const float* wsrc = wgt + (size_t)(g * OCPT) * IC * 9;
        for (int i = tid; i < IC * 9 * OCPT; i += 128) {
            const int ocl = i % OCPT;
            const int t   = (i / OCPT) % 9;
            const int ic  = i / (OCPT * 9);
            ws[i] = wsrc[((size_t)ocl * IC + ic) * 9 + t];
        }
    }
    __syncthreads();

    unsigned long long acc[NOP][PXC];
#pragma unroll
    for (int op = 0; op < NOP; op++)
#pragma unroll
        for (int p = 0; p < PXC; p++) acc[op][p] = 0ULL;

    const float* inb = in + (size_t)b * IC * planeI;

#pragma unroll 1
    for (int ic = 0; ic < IC; ic++) {
        const float* plane = inb + (size_t)ic * planeI;
#pragma unroll
        for (int ky = 0; ky < 3; ky++) {
            const float* rp = plane + (size_t)(oy * STRIDE + ky) * PWI
                                    + (size_t)x0 * STRIDE;
            unsigned long long pk[NIN];
            {
                float v[NV2 * 2];
#pragma unroll
                for (int i = 0; i < NV2; i++) {
                    const float2 t2 = *(const float2*)(rp + 2 * i);
                    v[2 * i]     = t2.x;
                    v[2 * i + 1] = t2.y;
                }
#pragma unroll
                for (int c = 0; c < NIN; c++) pk[c] = pack2(v[c]);
            }
#pragma unroll
            for (int kx = 0; kx < 3; kx++) {
                const float* wr = ws + (ic * 9 + ky * 3 + kx) * OCPT;
                unsigned long long w2[NOP];
#pragma unroll
                for (int j = 0; j < NF4; j++) {
                    const float4 wf = *(const float4*)(wr + 4 * j);
                    unsigned long long lo, hi;
                    asm("mov.b64 %0, {%1, %2};" : "=l"(lo)
                        : "f"(wf.x), "f"(wf.y));
                    asm("mov.b64 %0, {%1, %2};" : "=l"(hi)
                        : "f"(wf.z), "f"(wf.w));
                    w2[2 * j]     = lo;
                    w2[2 * j + 1] = hi;
                }
#pragma unroll
                for (int p = 0; p < PXC; p++) {
                    const unsigned long long xv = pk[p * STRIDE + kx];
#pragma unroll
                    for (int op = 0; op < NOP; op++)
                        FMA2(acc[op][p], w2[op], xv);
                }
            }
        }
    }

    const float inv = rsqrtf(1.f + 1e-5f);
#pragma unroll
    for (int op = 0; op < NOP; op++) {
        const int oc = g * OCPT + 2 * op;
        const float s0 = gamma[oc] * inv,  s1 = gamma[oc + 1] * inv;
        const float c0 = beta[oc],         c1 = beta[oc + 1];
        float* o0 = out + (size_t)(b * OC + oc) * planeO
                        + (size_t)(oy + 1) * PWO + 1;
        float* o1 = o0 + planeO;
#pragma unroll
        for (int p = 0; p < PXC; p++) {
            if (x0 + p < OW) {
                float2 a;
                memcpy(&a, &acc[op][p], 8);
                o0[x0 + p] = fmaxf(fmaf(a.x, s0, c0), 0.f);
                o1[x0 + p] = fmaxf(fmaf(a.y, s1, c1), 0.f);
            }
        }
    }
}

// ---------------------------------------------------------------------------
// Copy image into padded scratch (interior only; halo stays zero)
// ---------------------------------------------------------------------------
__global__ void pad_image(const float* __restrict__ img)
{
    const int idx = blockIdx.x * blockDim.x + threadIdx.x;
    const int total = BATCH * 3 * IMG_H * IMG_W;
    if (idx >= total) return;
    const int x = idx % IMG_W;
    int r = idx / IMG_W;
    const int y = r % IMG_H;
    const int p = r / IMG_H;          // b*3 + c
    g_imgp[(size_t)p * PLANE0 + (size_t)(y + 1) * PW0 + (x + 1)] = img[idx];
}

// ---------------------------------------------------------------------------
// 1x1 conv (96 -> 1) + bias (reads padded feature maps).
// mode 0: raw logits (hm). mode 1: depth transform.
// ---------------------------------------------------------------------------
template<int MODE>
__global__ void head1x1(const float* __restrict__ feat,
                        const float* __restrict__ w,
                        const float* __restrict__ bias,
                        float* __restrict__ out)
{
    const int idx = blockIdx.x * blockDim.x + threadIdx.x;
    if (idx >= BATCH * NPIX) return;
    const int b = idx / NPIX;
    const int p = idx % NPIX;
    const int y = p / FW;
    const int x = p % FW;
    float s = bias[0];
    const float* fb = feat + (size_t)b * 96 * PLANE3
                           + (size_t)(y + 1) * PW3 + (x + 1);
#pragma unroll 8
    for (int ic = 0; ic < 96; ic++)
        s += fb[(size_t)ic * PLANE3] * w[ic];
    if (MODE == 0) {
        out[idx] = s;
    } else {
        const float sig = 1.f / (1.f + expf(-s));
        out[idx] = 1.0f + sig * 79.0f;   // DMIN + sig*(DMAX-DMIN)
    }
}

// ---------------------------------------------------------------------------
// Zero the BEV accumulation region
// ---------------------------------------------------------------------------
__global__ void zero_bev(float* __restrict__ bev)
{
    const int i = blockIdx.x * blockDim.x + threadIdx.x;
    if (i < BEV_SZ) bev[i] = 0.f;
}

// ---------------------------------------------------------------------------
// Per-batch top-200 (iterative block argmax, lowest-index tie break) + splat.
// ---------------------------------------------------------------------------
__global__ void __launch_bounds__(1024, 1)
topk_splat(const float* __restrict__ hm,
           const float* __restrict__ depth,
           const float* __restrict__ P,
           const float* __restrict__ T,
           float* __restrict__ bev)
{
    const int b    = blockIdx.x;
    const int tid  = threadIdx.x;
    const int lane = tid & 31;
    const int warp = tid >> 5;

    __shared__ float prob[NPIX];
    __shared__ float sscore[TOPK];
    __shared__ int   sidx[TOPK];
    __shared__ float wv[32];
    __shared__ int   wi[32];

    for (int i = tid; i < NPIX; i += blockDim.x) {
        const float x = hm[b * NPIX + i];
        prob[i] = 1.f / (1.f + expf(-x));
    }
    __syncthreads();

    for (int k = 0; k < TOPK; k++) {
        float v = -1.f; int bi = NPIX;
        for (int i = tid; i < NPIX; i += blockDim.x) {
            const float p = prob[i];
            if (p > v || (p == v && i < bi)) { v = p; bi = i; }
        }
#pragma unroll
        for (int off = 16; off > 0; off >>= 1) {
            const float ov = __shfl_down_sync(0xffffffffu, v, off);
            const int   oi = __shfl_down_sync(0xffffffffu, bi, off);
            if (ov > v || (ov == v && oi < bi)) { v = ov; bi = oi; }
        }
        if (lane == 0) { wv[warp] = v; wi[warp] = bi; }
        __syncthreads();
        if (warp == 0) {
            v  = wv[lane];
            bi = wi[lane];
#pragma unroll
            for (int off = 16; off > 0; off >>= 1) {
                const float ov = __shfl_down_sync(0xffffffffu, v, off);
                const int   oi = __shfl_down_sync(0xffffffffu, bi, off);
                if (ov > v || (ov == v && oi < bi)) { v = ov; bi = oi; }
            }
            if (lane == 0) {
                sscore[k] = v;
                sidx[k]   = bi;
                prob[bi]  = -1.f;
            }
        }
        __syncthreads();
    }

    if (tid < TOPK) {
        const int   idx   = sidx[tid];
        const float score = sscore[tid];
        const int ys = idx / FW;
        const int xs = idx % FW;
        const float d = depth[b * NPIX + idx];
        const float u = (xs + 0.5f) * ((float)IMG_W / (float)FW);
        const float v = (ys + 0.5f) * ((float)IMG_H / (float)FH);

        const float* Pb = P + b * 12;
        const float fx = fmaxf(Pb[0], EPSV);
        const float fy = fmaxf(Pb[5], EPSV);
        const float cx = Pb[2], cy = Pb[6];
        const float tx = Pb[3], ty = Pb[7];
        const float xc = (u * d - cx * d - tx) / fx;
        const float yc = (v * d - cy * d - ty) / fy;

        const float* Tb = T + b * 16;
        const float lx = Tb[0]*xc + Tb[1]*yc + Tb[2]*d + Tb[3];
        const float ly = Tb[4]*xc + Tb[5]*yc + Tb[6]*d + Tb[7];

        const int gx = (int)floorf((lx + 51.2f) / 0.2f);
        const int gy = (int)floorf((ly + 51.2f) / 0.2f);

        const bool valid = (score >= THR) && (gx >= 0) && (gx < BEV)
                                          && (gy >= 0) && (gy < BEV);
        if (valid) {
            const float isig = 18.f / 25.f;   // 1/(2*sigma^2), sigma=5/6
            float* bb = bev + (size_t)b * BEV * BEV;
#pragma unroll
            for (int dy = -2; dy <= 2; dy++) {
                const int iy = gy + dy;
                if (iy < 0 || iy >= BEV) continue;
#pragma unroll
                for (int dx = -2; dx <= 2; dx++) {
                    const int ix = gx + dx;
                    if (ix < 0 || ix >= BEV) continue;
                    const float val = score * expf(-(float)(dy*dy + dx*dx) * isig);
                    atomicMax((int*)&bb[iy * BEV + ix], __float_as_int(val));
                }
            }
        }
    }
}

// ---------------------------------------------------------------------------
// Finalize: clip to prob, compute logits.
// ---------------------------------------------------------------------------
__global__ void finalize_bev(float* __restrict__ out)
{
    const int i = blockIdx.x * blockDim.x + threadIdx.x;
    if (i >= BEV_SZ) return;
    float p = out[OFF_PROB + i];
    p = fminf(fmaxf(p, EPSV), 1.f - EPSV);
    out[OFF_PROB + i]   = p;
    out[OFF_LOGITS + i] = logf(p) - log1pf(-p);
}

// ---------------------------------------------------------------------------
// Launcher
// ---------------------------------------------------------------------------
extern "C" void kernel_launch(void* const* d_in, const int* in_sizes, int n_in,
                              void* d_out, int out_size)
{
    (void)in_sizes; (void)n_in; (void)out_size;

    const float* image = (const float*)d_in[0];
    const float* P     = (const float*)d_in[1];
    const float* T     = (const float*)d_in[2];
    const float* W1  = (const float*)d_in[3];
    const float* g1  = (const float*)d_in[4];
    const float* b1  = (const float*)d_in[5];
    const float* W2  = (const float*)d_in[6];
    const float* g2  = (const float*)d_in[7];
    const float* b2  = (const float*)d_in[8];
    const float* W3  = (const float*)d_in[9];
    const float* g3  = (const float*)d_in[10];
    const float* b3  = (const float*)d_in[11];
    const float* Wh1 = (const float*)d_in[12];
    const float* gh1 = (const float*)d_in[13];
    const float* bh1 = (const float*)d_in[14];
    const float* Wh2 = (const float*)d_in[15];
    const float* bh2 = (const float*)d_in[16];
    const float* Wd1 = (const float*)d_in[17];
    const float* gd1 = (const float*)d_in[18];
    const float* bd1 = (const float*)d_in[19];
    const float* Wd2 = (const float*)d_in[20];
    const float* bd2 = (const float*)d_in[21];

    float* out = (float*)d_out;

    float *imgp, *x1, *x2, *feats, *h1, *d1;
    cudaGetSymbolAddress((void**)&imgp,  g_imgp);
    cudaGetSymbolAddress((void**)&x1,    g_x1);
    cudaGetSymbolAddress((void**)&x2,    g_x2);
    cudaGetSymbolAddress((void**)&feats, g_feats);
    cudaGetSymbolAddress((void**)&h1,    g_h1);
    cudaGetSymbolAddress((void**)&d1,    g_d1);

    // pad image into halo scratch
    {
        const int total = BATCH * 3 * IMG_H * IMG_W;
        pad_image<<<(total + 255) / 256, 256>>>(image);
    }

    dim3 blk(32, 4);

    // conv1: 3 -> 32, stride 2  (512x1408 -> 256x704), OCPT=16, PXC=4
    convp<3, 32, 16, 2, 4, 0><<<dim3(6, 64, BATCH * 2), blk>>>(
        imgp, PW0, PLANE0, 256, 704, PW1, PLANE1,
        W1, g1, b1, x1, nullptr, nullptr, nullptr, nullptr);

    // conv2: 32 -> 64, stride 2  (256x704 -> 128x352), OCPT=16, PXC=4
    convp<32, 64, 16, 2, 4, 0><<<dim3(3, 32, BATCH * 4), blk>>>(
        x1, PW1, PLANE1, 128, 352, PW2, PLANE2,
        W2, g2, b2, x2, nullptr, nullptr, nullptr, nullptr);

    // conv3: 64 -> 96, stride 2  (128x352 -> 64x176), OCPT=12, PXC=6
    convp<64, 96, 12, 2, 6, 0><<<dim3(1, 16, BATCH * 8), blk>>>(
        x2, PW2, PLANE2, 64, 176, PW3, PLANE3,
        W3, g3, b3, feats, nullptr, nullptr, nullptr, nullptr);

    // both head hidden convs (fused): 96 -> 96, stride 1, OCPT=12, PXC=6
    convp<96, 96, 12, 1, 6, 1><<<dim3(1, 16, BATCH * 2 * 8), blk>>>(
        feats, PW3, PLANE3, 64, 176, PW3, PLANE3,
        Wh1, gh1, bh1, h1, Wd1, gd1, bd1, d1);

    // 1x1 heads
    head1x1<0><<<(BATCH * NPIX + 255) / 256, 256>>>(h1, Wh2, bh2, out + OFF_HM);
    head1x1<1><<<(BATCH * NPIX + 255) / 256, 256>>>(d1, Wd2, bd2, out + OFF_DEPTH);

    // BEV accumulate (prob region), splat, finalize
    zero_bev<<<(BEV_SZ + 255) / 256, 256>>>(out + OFF_PROB);
    topk_splat<<<BATCH, 1024>>>(out + OFF_HM, out + OFF_DEPTH, P, T, out + OFF_PROB);
    finalize_bev<<<(BEV_SZ + 255) / 256, 256>>>(out);
}